// round 7
// baseline (speedup 1.0000x reference)
#include <cuda_runtime.h>

#define MAX_NODES 50000
#define NFEAT 256
#define NHID  256
#define NOUT  128
#define MAX_EDGES 800000

// ---------------- scratch (device globals; no allocation allowed) -------------
__device__ __align__(16) float g_s1[MAX_NODES * NHID];   // x @ w1
__device__ __align__(16) float g_h [MAX_NODES * NHID];   // aggregated hidden (pre-relu)
__device__ __align__(16) float g_s2[MAX_NODES * NOUT];   // relu(h) @ w2
__device__ int g_count [MAX_NODES + 1];
__device__ int g_row   [MAX_NODES + 1];
__device__ int g_cursor[MAX_NODES + 1];
__device__ int g_csr_src[MAX_EDGES];

// ---------------- CSR build (by destination) ----------------------------------
__global__ void zero_count_kernel(int n) {
    int i = blockIdx.x * blockDim.x + threadIdx.x;
    if (i < n) g_count[i] = 0;
}

__global__ void hist_kernel(const int* __restrict__ dst, int ne) {
    int i = blockIdx.x * blockDim.x + threadIdx.x;
    if (i < ne) atomicAdd(&g_count[dst[i]], 1);
}

// single-block exclusive scan over n counters (n <= ~1M easily fine here)
__global__ void scan_kernel(int n) {
    __shared__ int s[1024];
    int t = threadIdx.x;
    int chunk = (n + 1023) >> 10;
    int beg = t * chunk;
    int end = min(beg + chunk, n);
    int sum = 0;
    for (int i = beg; i < end; i++) sum += g_count[i];
    s[t] = sum;
    __syncthreads();
    // Hillis-Steele inclusive scan over 1024 partials
    for (int off = 1; off < 1024; off <<= 1) {
        int v = (t >= off) ? s[t - off] : 0;
        __syncthreads();
        s[t] += v;
        __syncthreads();
    }
    int run = (t == 0) ? 0 : s[t - 1];
    for (int i = beg; i < end; i++) {
        g_row[i]    = run;
        g_cursor[i] = run;
        run += g_count[i];
    }
    if (t == 1023) g_row[n] = run;   // total = ne
}

__global__ void fill_kernel(const int* __restrict__ src, const int* __restrict__ dst, int ne) {
    int i = blockIdx.x * blockDim.x + threadIdx.x;
    if (i < ne) {
        int d = dst[i];
        int pos = atomicAdd(&g_cursor[d], 1);
        g_csr_src[pos] = src[i];
    }
}

// ---------------- tiled fp32 GEMM: C[M,N] = A[M,K] @ B[K,N] -------------------
// TM=128, TN=64, TK=32, 256 threads, 8x4 micro-tile per thread.
template<bool RELU_A>
__device__ __forceinline__ void gemm_body(const float* __restrict__ A,
                                          const float* __restrict__ B,
                                          float* __restrict__ C,
                                          int M, int N, int K) {
    __shared__ float As[32][129];   // transposed A tile: As[k][m], +1 pad
    __shared__ float Bs[32][64];    // Bs[k][n]

    int tid = threadIdx.x;
    int tx = tid & 15;              // 16 col-groups of 4
    int ty = tid >> 4;              // 16 row-groups of 8
    int brow = blockIdx.y * 128;
    int bcol = blockIdx.x * 64;

    float acc[8][4];
#pragma unroll
    for (int i = 0; i < 8; i++)
#pragma unroll
        for (int j = 0; j < 4; j++) acc[i][j] = 0.f;

    for (int k0 = 0; k0 < K; k0 += 32) {
        // load A tile 128x32 (1024 float4s, 4 per thread), store transposed
#pragma unroll
        for (int i = 0; i < 4; i++) {
            int lin = tid + i * 256;          // 0..1023
            int r   = lin >> 3;               // 0..127
            int c4  = lin & 7;                // float4 column
            int grow = brow + r;
            float4 v = make_float4(0.f, 0.f, 0.f, 0.f);
            if (grow < M)
                v = *(const float4*)(A + (size_t)grow * K + k0 + (c4 << 2));
            if (RELU_A) {
                v.x = fmaxf(v.x, 0.f); v.y = fmaxf(v.y, 0.f);
                v.z = fmaxf(v.z, 0.f); v.w = fmaxf(v.w, 0.f);
            }
            As[(c4 << 2) + 0][r] = v.x;
            As[(c4 << 2) + 1][r] = v.y;
            As[(c4 << 2) + 2][r] = v.z;
            As[(c4 << 2) + 3][r] = v.w;
        }
        // load B tile 32x64 (512 float4s, 2 per thread)
#pragma unroll
        for (int i = 0; i < 2; i++) {
            int lin = tid + i * 256;          // 0..511
            int r   = lin >> 4;               // 0..31
            int c4  = lin & 15;               // 0..15
            *(float4*)&Bs[r][c4 << 2] =
                *(const float4*)(B + (size_t)(k0 + r) * N + bcol + (c4 << 2));
        }
        __syncthreads();

#pragma unroll
        for (int k = 0; k < 32; k++) {
            float a[8];
#pragma unroll
            for (int i = 0; i < 8; i++) a[i] = As[k][(ty << 3) + i];
            float4 b = *(const float4*)&Bs[k][tx << 2];
            float bb[4] = {b.x, b.y, b.z, b.w};
#pragma unroll
            for (int i = 0; i < 8; i++)
#pragma unroll
                for (int j = 0; j < 4; j++)
                    acc[i][j] = fmaf(a[i], bb[j], acc[i][j]);
        }
        __syncthreads();
    }

#pragma unroll
    for (int i = 0; i < 8; i++) {
        int row = brow + (ty << 3) + i;
        if (row < M) {
            float4 v = make_float4(acc[i][0], acc[i][1], acc[i][2], acc[i][3]);
            *(float4*)(C + (size_t)row * N + bcol + (tx << 2)) = v;
        }
    }
}

__global__ __launch_bounds__(256) void gemm1_kernel(const float* __restrict__ A,
                                                    const float* __restrict__ B, int M) {
    gemm_body<false>(A, B, g_s1, M, NHID, NFEAT);
}
__global__ __launch_bounds__(256) void gemm2_kernel(const float* __restrict__ B, int M) {
    gemm_body<true>(g_h, B, g_s2, M, NOUT, NHID);   // ReLU fused into A load
}

// ---------------- CSR gather-sum (segment_sum without atomics) ----------------
// thread i -> (node = i >> LOGF4, float4 lane = i & mask); sums over node's edges.
template<int LOGF4>
__device__ __forceinline__ void gather_body(const float4* __restrict__ sup,
                                            float4* __restrict__ out, int n) {
    int i = blockIdx.x * blockDim.x + threadIdx.x;
    int node = i >> LOGF4;
    if (node >= n) return;
    int c = i & ((1 << LOGF4) - 1);
    int beg = g_row[node];
    int end = g_row[node + 1];
    float4 acc = make_float4(0.f, 0.f, 0.f, 0.f);
    int j = beg;
    for (; j + 1 < end; j += 2) {
        int s0 = g_csr_src[j];
        int s1 = g_csr_src[j + 1];
        float4 v0 = sup[((size_t)s0 << LOGF4) + c];
        float4 v1 = sup[((size_t)s1 << LOGF4) + c];
        acc.x += v0.x + v1.x; acc.y += v0.y + v1.y;
        acc.z += v0.z + v1.z; acc.w += v0.w + v1.w;
    }
    if (j < end) {
        int s0 = g_csr_src[j];
        float4 v0 = sup[((size_t)s0 << LOGF4) + c];
        acc.x += v0.x; acc.y += v0.y; acc.z += v0.z; acc.w += v0.w;
    }
    out[((size_t)node << LOGF4) + c] = acc;
}

__global__ void gather1_kernel(int n) {          // 256 feats -> 64 float4 lanes
    gather_body<6>((const float4*)g_s1, (float4*)g_h, n);
}
__global__ void gather2_kernel(float4* __restrict__ out, int n) {  // 128 feats -> 32 lanes
    gather_body<5>((const float4*)g_s2, out, n);
}

// ---------------- launch -------------------------------------------------------
extern "C" void kernel_launch(void* const* d_in, const int* in_sizes, int n_in,
                              void* d_out, int out_size) {
    const float* x    = (const float*)d_in[0];
    const float* w1   = (const float*)d_in[1];
    const float* w2   = (const float*)d_in[2];
    const int*   esrc = (const int*)d_in[3];
    const int*   edst = (const int*)d_in[4];
    int n  = in_sizes[0] / NFEAT;
    int ne = in_sizes[3];

    // CSR build (shared by both layers)
    zero_count_kernel<<<(n + 255) / 256, 256>>>(n);
    hist_kernel<<<(ne + 255) / 256, 256>>>(edst, ne);
    scan_kernel<<<1, 1024>>>(n);
    fill_kernel<<<(ne + 255) / 256, 256>>>(esrc, edst, ne);

    // layer 1: s1 = x @ w1 ; h = A·s1
    gemm1_kernel<<<dim3(NHID / 64, (n + 127) / 128), 256>>>(x, w1, n);
    gather1_kernel<<<(n * 64 + 255) / 256, 256>>>(n);

    // layer 2: s2 = relu(h) @ w2 ; out = A·s2
    gemm2_kernel<<<dim3(NOUT / 64, (n + 127) / 128), 256>>>(w2, n);
    gather2_kernel<<<(n * 32 + 255) / 256, 256>>>((float4*)d_out, n);
}

// round 11
// speedup vs baseline: 1.2954x; 1.2954x over previous
#include <cuda_runtime.h>
#include <cuda_bf16.h>

#define MAX_NODES 50000
#define NFEAT 256
#define NHID  256
#define NOUT  128
#define MAX_EDGES 800000

// ---------------- scratch (device globals; no allocation allowed) -------------
__device__ __align__(16) __nv_bfloat16 g_xh[MAX_NODES * NFEAT];
__device__ __align__(16) __nv_bfloat16 g_xl[MAX_NODES * NFEAT];
__device__ __align__(16) float         g_s1[MAX_NODES * NHID];   // x @ w1 (fp32)
__device__ __align__(16) __nv_bfloat16 g_hh[MAX_NODES * NHID];   // relu(agg) hi
__device__ __align__(16) __nv_bfloat16 g_hl[MAX_NODES * NHID];   // relu(agg) lo
__device__ __align__(16) float         g_s2[MAX_NODES * NOUT];   // h @ w2 (fp32)
__device__ __align__(16) __nv_bfloat16 g_w1h[NHID * NFEAT];      // w1^T [N][K]
__device__ __align__(16) __nv_bfloat16 g_w1l[NHID * NFEAT];
__device__ __align__(16) __nv_bfloat16 g_w2h[NOUT * NHID];       // w2^T [N][K]
__device__ __align__(16) __nv_bfloat16 g_w2l[NOUT * NHID];
__device__ int g_count [MAX_NODES + 1];
__device__ int g_row   [MAX_NODES + 1];
__device__ int g_cursor[MAX_NODES + 1];
__device__ int g_csr_src[MAX_EDGES];

// ---------------- small helpers ------------------------------------------------
__device__ __forceinline__ unsigned s2u(const void* p) {
    return (unsigned)__cvta_generic_to_shared(p);
}
__device__ __forceinline__ void ldsm_x4(unsigned* r, unsigned saddr) {
    asm volatile("ldmatrix.sync.aligned.m8n8.x4.shared.b16 {%0,%1,%2,%3}, [%4];"
                 : "=r"(r[0]), "=r"(r[1]), "=r"(r[2]), "=r"(r[3]) : "r"(saddr));
}
__device__ __forceinline__ void mma_bf16(float* c, const unsigned* a, const unsigned* b) {
    asm volatile("mma.sync.aligned.m16n8k16.row.col.f32.bf16.bf16.f32 "
                 "{%0,%1,%2,%3}, {%4,%5,%6,%7}, {%8,%9}, {%0,%1,%2,%3};"
                 : "+f"(c[0]), "+f"(c[1]), "+f"(c[2]), "+f"(c[3])
                 : "r"(a[0]), "r"(a[1]), "r"(a[2]), "r"(a[3]),
                   "r"(b[0]), "r"(b[1]));
}
// split fp32 pair into bf16 hi pair + lo pair
__device__ __forceinline__ __nv_bfloat162 split_pair(float a, float b, __nv_bfloat162& lo) {
    __nv_bfloat16 ah = __float2bfloat16(a);
    __nv_bfloat16 bh = __float2bfloat16(b);
    __nv_bfloat16 al = __float2bfloat16(a - __bfloat162float(ah));
    __nv_bfloat16 bl = __float2bfloat16(b - __bfloat162float(bh));
    lo = __nv_bfloat162(al, bl);
    return __nv_bfloat162(ah, bh);
}

// ---------------- CSR build (by destination) ----------------------------------
__global__ void zero_count_kernel(int n) {
    int i = blockIdx.x * blockDim.x + threadIdx.x;
    if (i < n) g_count[i] = 0;
}
__global__ void hist_kernel(const int* __restrict__ dst, int ne) {
    int i = blockIdx.x * blockDim.x + threadIdx.x;
    if (i < ne) atomicAdd(&g_count[dst[i]], 1);
}
__global__ void scan_kernel(int n) {
    __shared__ int s[1024];
    int t = threadIdx.x;
    int chunk = (n + 1023) >> 10;
    int beg = t * chunk;
    int end = min(beg + chunk, n);
    int sum = 0;
    for (int i = beg; i < end; i++) sum += g_count[i];
    s[t] = sum;
    __syncthreads();
    for (int off = 1; off < 1024; off <<= 1) {
        int v = (t >= off) ? s[t - off] : 0;
        __syncthreads();
        s[t] += v;
        __syncthreads();
    }
    int run = (t == 0) ? 0 : s[t - 1];
    for (int i = beg; i < end; i++) {
        g_row[i]    = run;
        g_cursor[i] = run;
        run += g_count[i];
    }
    if (t == 1023) g_row[n] = run;
}
__global__ void fill_kernel(const int* __restrict__ src, const int* __restrict__ dst, int ne) {
    int i = blockIdx.x * blockDim.x + threadIdx.x;
    if (i < ne) {
        int d = dst[i];
        int pos = atomicAdd(&g_cursor[d], 1);
        g_csr_src[pos] = src[i];
    }
}

// ---------------- fp32 -> bf16 hi/lo split kernels ------------------------------
__global__ void split_x_kernel(const float4* __restrict__ x, int n4) {
    int i = blockIdx.x * blockDim.x + threadIdx.x;
    if (i >= n4) return;
    float4 v = x[i];
    __nv_bfloat162 l01, l23;
    __nv_bfloat162 h01 = split_pair(v.x, v.y, l01);
    __nv_bfloat162 h23 = split_pair(v.z, v.w, l23);
    ((__nv_bfloat162*)g_xh)[i * 2 + 0] = h01;
    ((__nv_bfloat162*)g_xh)[i * 2 + 1] = h23;
    ((__nv_bfloat162*)g_xl)[i * 2 + 0] = l01;
    ((__nv_bfloat162*)g_xl)[i * 2 + 1] = l23;
}
// w[K][Nn] row-major -> th/tl [Nn][K] (transposed, k-contiguous)
__global__ void split_wt_kernel(const float* __restrict__ w,
                                __nv_bfloat16* __restrict__ th,
                                __nv_bfloat16* __restrict__ tl, int K, int Nn) {
    int idx = blockIdx.x * blockDim.x + threadIdx.x;
    if (idx >= K * Nn) return;
    int k = idx / Nn, nn = idx % Nn;
    float v = w[idx];
    __nv_bfloat16 h = __float2bfloat16(v);
    th[nn * K + k] = h;
    tl[nn * K + k] = __float2bfloat16(v - __bfloat162float(h));
}

// ---------------- tensor-core GEMM: C[M,N] = (Ah+Al)[M,K] @ (Bh+Bl)^T ----------
// A: [M][K] bf16 row-major. Bt: [N][K] bf16 (k-contiguous). 3-MMA split.
// BM=128 BN=64 BK=32, 256 threads (8 warps = 4x2 of 32x32 warp tiles).
#define ASTR 40   // smem row stride in bf16 (80B = 5 x 16B, odd -> conflict-free ldmatrix)

__global__ __launch_bounds__(256) void gemm_bf16x3_kernel(
    const __nv_bfloat16* __restrict__ Ah, const __nv_bfloat16* __restrict__ Al,
    const __nv_bfloat16* __restrict__ Bh, const __nv_bfloat16* __restrict__ Bl,
    float* __restrict__ C, int M, int N, int K)
{
    __shared__ __nv_bfloat16 sAh[128 * ASTR];
    __shared__ __nv_bfloat16 sAl[128 * ASTR];
    __shared__ __nv_bfloat16 sBh[64 * ASTR];
    __shared__ __nv_bfloat16 sBl[64 * ASTR];

    int tid = threadIdx.x;
    int lane = tid & 31;
    int wid = tid >> 5;
    int warp_m = wid & 3;   // 0..3  -> m offset *32
    int warp_n = wid >> 2;  // 0..1  -> n offset *32
    int brow = blockIdx.y * 128;
    int bcol = blockIdx.x * 64;

    float acc[2][4][4];
#pragma unroll
    for (int mi = 0; mi < 2; mi++)
#pragma unroll
        for (int j = 0; j < 4; j++)
#pragma unroll
            for (int e = 0; e < 4; e++) acc[mi][j][e] = 0.f;

    // ldmatrix source addresses (per-thread, fixed over k loop up to offsets)
    int a_row = warp_m * 32 + (lane & 15);
    int a_c8  = ((lane >> 4) & 1) * 8;
    unsigned aBaseH = s2u(sAh) + (unsigned)(a_row * ASTR + a_c8) * 2;
    unsigned aBaseL = s2u(sAl) + (unsigned)(a_row * ASTR + a_c8) * 2;
    int b_row = warp_n * 32 + (lane & 7) + ((lane >> 4) & 1) * 8;
    int b_c8  = ((lane >> 3) & 1) * 8;
    unsigned bBaseH = s2u(sBh) + (unsigned)(b_row * ASTR + b_c8) * 2;
    unsigned bBaseL = s2u(sBl) + (unsigned)(b_row * ASTR + b_c8) * 2;

    const uint4 z4 = make_uint4(0, 0, 0, 0);

    for (int k0 = 0; k0 < K; k0 += 32) {
        // ---- load A tiles (128x32 per split): 2 x uint4 per thread per split
#pragma unroll
        for (int i = 0; i < 2; i++) {
            int lin = tid + i * 256;
            int r = lin >> 2, c = lin & 3;
            int grow = brow + r;
            uint4 vh = z4, vl = z4;
            if (grow < M) {
                vh = *(const uint4*)(Ah + (size_t)grow * K + k0 + c * 8);
                vl = *(const uint4*)(Al + (size_t)grow * K + k0 + c * 8);
            }
            ((uint4*)sAh)[r * 5 + c] = vh;   // ASTR bf16 = 5 uint4
            ((uint4*)sAl)[r * 5 + c] = vl;
        }
        // ---- load B tiles (64x32 per split): 1 x uint4 per thread per split
        {
            int r = tid >> 2, c = tid & 3;
            ((uint4*)sBh)[r * 5 + c] = *(const uint4*)(Bh + (size_t)(bcol + r) * K + k0 + c * 8);
            ((uint4*)sBl)[r * 5 + c] = *(const uint4*)(Bl + (size_t)(bcol + r) * K + k0 + c * 8);
        }
        __syncthreads();

#pragma unroll
        for (int ks = 0; ks < 32; ks += 16) {
            unsigned ah[2][4], al[2][4], bh[2][4], bl[2][4];
            ldsm_x4(ah[0], aBaseH + (unsigned)(ks) * 2);
            ldsm_x4(ah[1], aBaseH + (unsigned)(16 * ASTR + ks) * 2);
            ldsm_x4(al[0], aBaseL + (unsigned)(ks) * 2);
            ldsm_x4(al[1], aBaseL + (unsigned)(16 * ASTR + ks) * 2);
            ldsm_x4(bh[0], bBaseH + (unsigned)(ks) * 2);
            ldsm_x4(bh[1], bBaseH + (unsigned)(16 * ASTR + ks) * 2);
            ldsm_x4(bl[0], bBaseL + (unsigned)(ks) * 2);
            ldsm_x4(bl[1], bBaseL + (unsigned)(16 * ASTR + ks) * 2);
#pragma unroll
            for (int mi = 0; mi < 2; mi++) {
#pragma unroll
                for (int j = 0; j < 4; j++) {
                    const unsigned* bhp = &bh[j >> 1][(j & 1) * 2];
                    const unsigned* blp = &bl[j >> 1][(j & 1) * 2];
                    mma_bf16(acc[mi][j], ah[mi], bhp);   // Ah*Bh
                    mma_bf16(acc[mi][j], ah[mi], blp);   // Ah*Bl
                    mma_bf16(acc[mi][j], al[mi], bhp);   // Al*Bh
                }
            }
        }
        __syncthreads();
    }

    // ---- epilogue: fp32 fragment writes
    int r_base = brow + warp_m * 32 + (lane >> 2);
    int c_base = bcol + warp_n * 32 + (lane & 3) * 2;
#pragma unroll
    for (int mi = 0; mi < 2; mi++) {
#pragma unroll
        for (int j = 0; j < 4; j++) {
            int cc = c_base + j * 8;
            int r0 = r_base + mi * 16;
            if (r0 < M)
                *(float2*)(C + (size_t)r0 * N + cc) = make_float2(acc[mi][j][0], acc[mi][j][1]);
            int r1 = r0 + 8;
            if (r1 < M)
                *(float2*)(C + (size_t)r1 * N + cc) = make_float2(acc[mi][j][2], acc[mi][j][3]);
        }
    }
}

// ---------------- CSR gather-sum ------------------------------------------------
// layer1: sum fp32 s1 rows -> relu -> bf16 hi/lo split (fused), 64 float4 lanes/node
__global__ void gather1_kernel(int n) {
    int i = blockIdx.x * blockDim.x + threadIdx.x;
    int node = i >> 6;
    if (node >= n) return;
    int c = i & 63;
    const float4* sup = (const float4*)g_s1;
    int beg = g_row[node];
    int end = g_row[node + 1];
    float4 acc = make_float4(0.f, 0.f, 0.f, 0.f);
    int j = beg;
    for (; j + 1 < end; j += 2) {
        int s0 = g_csr_src[j];
        int s1 = g_csr_src[j + 1];
        float4 v0 = sup[((size_t)s0 << 6) + c];
        float4 v1 = sup[((size_t)s1 << 6) + c];
        acc.x += v0.x + v1.x; acc.y += v0.y + v1.y;
        acc.z += v0.z + v1.z; acc.w += v0.w + v1.w;
    }
    if (j < end) {
        int s0 = g_csr_src[j];
        float4 v0 = sup[((size_t)s0 << 6) + c];
        acc.x += v0.x; acc.y += v0.y; acc.z += v0.z; acc.w += v0.w;
    }
    // relu + bf16 split, write hi/lo
    acc.x = fmaxf(acc.x, 0.f); acc.y = fmaxf(acc.y, 0.f);
    acc.z = fmaxf(acc.z, 0.f); acc.w = fmaxf(acc.w, 0.f);
    __nv_bfloat162 l01, l23;
    __nv_bfloat162 h01 = split_pair(acc.x, acc.y, l01);
    __nv_bfloat162 h23 = split_pair(acc.z, acc.w, l23);
    size_t o = ((size_t)node << 8) + (c << 2);
    *(__nv_bfloat162*)(g_hh + o)     = h01;
    *(__nv_bfloat162*)(g_hh + o + 2) = h23;
    *(__nv_bfloat162*)(g_hl + o)     = l01;
    *(__nv_bfloat162*)(g_hl + o + 2) = l23;
}

// layer2: sum fp32 s2 rows -> d_out (fp32), 32 float4 lanes/node
__global__ void gather2_kernel(float4* __restrict__ out, int n) {
    int i = blockIdx.x * blockDim.x + threadIdx.x;
    int node = i >> 5;
    if (node >= n) return;
    int c = i & 31;
    const float4* sup = (const float4*)g_s2;
    int beg = g_row[node];
    int end = g_row[node + 1];
    float4 acc = make_float4(0.f, 0.f, 0.f, 0.f);
    int j = beg;
    for (; j + 1 < end; j += 2) {
        int s0 = g_csr_src[j];
        int s1 = g_csr_src[j + 1];
        float4 v0 = sup[((size_t)s0 << 5) + c];
        float4 v1 = sup[((size_t)s1 << 5) + c];
        acc.x += v0.x + v1.x; acc.y += v0.y + v1.y;
        acc.z += v0.z + v1.z; acc.w += v0.w + v1.w;
    }
    if (j < end) {
        int s0 = g_csr_src[j];
        float4 v0 = sup[((size_t)s0 << 5) + c];
        acc.x += v0.x; acc.y += v0.y; acc.z += v0.z; acc.w += v0.w;
    }
    out[((size_t)node << 5) + c] = acc;
}

// ---------------- launch --------------------------------------------------------
extern "C" void kernel_launch(void* const* d_in, const int* in_sizes, int n_in,
                              void* d_out, int out_size) {
    const float* x    = (const float*)d_in[0];
    const float* w1   = (const float*)d_in[1];
    const float* w2   = (const float*)d_in[2];
    const int*   esrc = (const int*)d_in[3];
    const int*   edst = (const int*)d_in[4];
    int n  = in_sizes[0] / NFEAT;
    int ne = in_sizes[3];

    __nv_bfloat16 *xh, *xl, *hh, *hl, *w1h, *w1l, *w2h, *w2l;
    float *s1, *s2;
    cudaGetSymbolAddress((void**)&xh,  g_xh);
    cudaGetSymbolAddress((void**)&xl,  g_xl);
    cudaGetSymbolAddress((void**)&hh,  g_hh);
    cudaGetSymbolAddress((void**)&hl,  g_hl);
    cudaGetSymbolAddress((void**)&w1h, g_w1h);
    cudaGetSymbolAddress((void**)&w1l, g_w1l);
    cudaGetSymbolAddress((void**)&w2h, g_w2h);
    cudaGetSymbolAddress((void**)&w2l, g_w2l);
    cudaGetSymbolAddress((void**)&s1,  g_s1);
    cudaGetSymbolAddress((void**)&s2,  g_s2);

    // bf16 hi/lo splits (x and transposed weights)
    int n4 = n * NFEAT / 4;
    split_x_kernel<<<(n4 + 255) / 256, 256>>>((const float4*)x, n4);
    split_wt_kernel<<<(NFEAT * NHID + 255) / 256, 256>>>(w1, w1h, w1l, NFEAT, NHID);
    split_wt_kernel<<<(NHID * NOUT + 255) / 256, 256>>>(w2, w2h, w2l, NHID, NOUT);

    // CSR build
    zero_count_kernel<<<(n + 255) / 256, 256>>>(n);
    hist_kernel<<<(ne + 255) / 256, 256>>>(edst, ne);
    scan_kernel<<<1, 1024>>>(n);
    fill_kernel<<<(ne + 255) / 256, 256>>>(esrc, edst, ne);

    // layer 1: s1 = x @ w1 (tensor core, 3-MMA split) ; h = relu(A*s1) -> bf16 split
    gemm_bf16x3_kernel<<<dim3(NHID / 64, (n + 127) / 128), 256>>>(
        xh, xl, w1h, w1l, s1, n, NHID, NFEAT);
    gather1_kernel<<<(n * 64 + 255) / 256, 256>>>(n);

    // layer 2: s2 = h @ w2 ; out = A*s2
    gemm_bf16x3_kernel<<<dim3(NOUT / 64, (n + 127) / 128), 256>>>(
        hh, hl, w2h, w2l, s2, n, NOUT, NHID);
    gather2_kernel<<<(n * 32 + 255) / 256, 256>>>((float4*)d_out, n);
}

// round 15
// speedup vs baseline: 1.4500x; 1.1193x over previous
#include <cuda_runtime.h>
#include <cuda_bf16.h>

#define MAX_NODES 50000
#define NFEAT 256
#define NHID  256
#define NOUT  128
#define MAX_EDGES 800000

// ---------------- scratch (device globals; no allocation allowed) -------------
__device__ __align__(16) float         g_s1[MAX_NODES * NHID];   // x @ w1 (fp32)
__device__ __align__(16) float         g_h [MAX_NODES * NHID];   // relu(agg) fp32
__device__ __align__(16) float         g_s2[MAX_NODES * NOUT];   // h @ w2 (fp32)
__device__ __align__(16) __nv_bfloat16 g_w1h[NHID * NFEAT];      // w1^T [N][K] hi
__device__ __align__(16) __nv_bfloat16 g_w1l[NHID * NFEAT];      // w1^T lo
__device__ __align__(16) __nv_bfloat16 g_w2h[NOUT * NHID];
__device__ __align__(16) __nv_bfloat16 g_w2l[NOUT * NHID];
__device__ int g_count [MAX_NODES + 1];
__device__ int g_row   [MAX_NODES + 1];
__device__ int g_cursor[MAX_NODES + 1];
__device__ int g_csr_src[MAX_EDGES];

// ---------------- small helpers ------------------------------------------------
__device__ __forceinline__ unsigned s2u(const void* p) {
    return (unsigned)__cvta_generic_to_shared(p);
}
__device__ __forceinline__ void ldsm_x4(unsigned* r, unsigned saddr) {
    asm volatile("ldmatrix.sync.aligned.m8n8.x4.shared.b16 {%0,%1,%2,%3}, [%4];"
                 : "=r"(r[0]), "=r"(r[1]), "=r"(r[2]), "=r"(r[3]) : "r"(saddr));
}
__device__ __forceinline__ void mma_bf16(float* c, const unsigned* a, const unsigned* b) {
    asm volatile("mma.sync.aligned.m16n8k16.row.col.f32.bf16.bf16.f32 "
                 "{%0,%1,%2,%3}, {%4,%5,%6,%7}, {%8,%9}, {%0,%1,%2,%3};"
                 : "+f"(c[0]), "+f"(c[1]), "+f"(c[2]), "+f"(c[3])
                 : "r"(a[0]), "r"(a[1]), "r"(a[2]), "r"(a[3]),
                   "r"(b[0]), "r"(b[1]));
}
__device__ __forceinline__ __nv_bfloat162 split_pair(float a, float b, __nv_bfloat162& lo) {
    __nv_bfloat16 ah = __float2bfloat16(a);
    __nv_bfloat16 bh = __float2bfloat16(b);
    __nv_bfloat16 al = __float2bfloat16(a - __bfloat162float(ah));
    __nv_bfloat16 bl = __float2bfloat16(b - __bfloat162float(bh));
    lo = __nv_bfloat162(al, bl);
    return __nv_bfloat162(ah, bh);
}

// ---------------- CSR build (by destination) ----------------------------------
__global__ void zero_count_kernel(int n) {
    int i = blockIdx.x * blockDim.x + threadIdx.x;
    if (i < n) g_count[i] = 0;
}
__global__ void hist_kernel(const int* __restrict__ dst, int ne) {
    int i = (blockIdx.x * blockDim.x + threadIdx.x) * 4;
#pragma unroll
    for (int j = 0; j < 4; j++)
        if (i + j < ne) atomicAdd(&g_count[dst[i + j]], 1);
}
__global__ void scan_kernel(int n) {
    __shared__ int s[1024];
    int t = threadIdx.x;
    int chunk = (n + 1023) >> 10;
    int beg = t * chunk;
    int end = min(beg + chunk, n);
    int sum = 0;
    for (int i = beg; i < end; i++) sum += g_count[i];
    s[t] = sum;
    __syncthreads();
    for (int off = 1; off < 1024; off <<= 1) {
        int v = (t >= off) ? s[t - off] : 0;
        __syncthreads();
        s[t] += v;
        __syncthreads();
    }
    int run = (t == 0) ? 0 : s[t - 1];
    for (int i = beg; i < end; i++) {
        g_row[i]    = run;
        g_cursor[i] = run;
        run += g_count[i];
    }
    if (t == 1023) g_row[n] = run;
}
__global__ void fill_kernel(const int* __restrict__ src, const int* __restrict__ dst, int ne) {
    int i = (blockIdx.x * blockDim.x + threadIdx.x) * 4;
#pragma unroll
    for (int j = 0; j < 4; j++) {
        if (i + j < ne) {
            int d = dst[i + j];
            int pos = atomicAdd(&g_cursor[d], 1);
            g_csr_src[pos] = src[i + j];
        }
    }
}

// ---------------- weight split: w[K][Nn] -> th/tl [Nn][K] ----------------------
__global__ void split_wt_kernel(const float* __restrict__ w,
                                __nv_bfloat16* __restrict__ th,
                                __nv_bfloat16* __restrict__ tl, int K, int Nn) {
    int idx = blockIdx.x * blockDim.x + threadIdx.x;
    if (idx >= K * Nn) return;
    int k = idx / Nn, nn = idx % Nn;
    float v = w[idx];
    __nv_bfloat16 h = __float2bfloat16(v);
    th[nn * K + k] = h;
    tl[nn * K + k] = __float2bfloat16(v - __bfloat162float(h));
}

// ---------------- tensor-core GEMM: C = A(fp32)[M,K] @ (Bh+Bl)^T ----------------
// A split into bf16 hi/lo on the fly during smem store (3-MMA reconstruction).
// BM=128 BN=64 BK=32, 256 threads, register-prefetch double buffering.
#define ASTR 40   // smem row stride in bf16 (80B, odd 16B-group stride -> conflict-free)

__global__ __launch_bounds__(256) void gemm_bf16x3_kernel(
    const float* __restrict__ A,
    const __nv_bfloat16* __restrict__ Bh, const __nv_bfloat16* __restrict__ Bl,
    float* __restrict__ C, int M, int N, int K)
{
    __shared__ __nv_bfloat16 sAh[128 * ASTR];
    __shared__ __nv_bfloat16 sAl[128 * ASTR];
    __shared__ __nv_bfloat16 sBh[64 * ASTR];
    __shared__ __nv_bfloat16 sBl[64 * ASTR];

    int tid = threadIdx.x;
    int lane = tid & 31;
    int wid = tid >> 5;
    int warp_m = wid & 3;
    int warp_n = wid >> 2;
    int brow = blockIdx.y * 128;
    int bcol = blockIdx.x * 64;

    float acc[2][4][4];
#pragma unroll
    for (int mi = 0; mi < 2; mi++)
#pragma unroll
        for (int j = 0; j < 4; j++)
#pragma unroll
            for (int e = 0; e < 4; e++) acc[mi][j][e] = 0.f;

    // ldmatrix per-thread addresses
    int a_row = warp_m * 32 + (lane & 15);
    int a_c8  = ((lane >> 4) & 1) * 8;
    unsigned aBaseH = s2u(sAh) + (unsigned)(a_row * ASTR + a_c8) * 2;
    unsigned aBaseL = s2u(sAl) + (unsigned)(a_row * ASTR + a_c8) * 2;
    int b_row = warp_n * 32 + (lane & 7) + ((lane >> 4) & 1) * 8;
    int b_c8  = ((lane >> 3) & 1) * 8;
    unsigned bBaseH = s2u(sBh) + (unsigned)(b_row * ASTR + b_c8) * 2;
    unsigned bBaseL = s2u(sBl) + (unsigned)(b_row * ASTR + b_c8) * 2;

    // global-load indices: A 128x32 fp32 = 1024 float4, 4 per thread
    int ra[4], ca[4];
#pragma unroll
    for (int i = 0; i < 4; i++) {
        int lin = tid + i * 256;
        ra[i] = lin >> 3;        // 0..127
        ca[i] = lin & 7;         // float4 column (4 fp32 k-values)
    }
    int rb = tid >> 2;           // 0..63
    int cb = tid & 3;            // uint4 column (8 bf16 k-values)

    float4 pa[4];
    uint4  pbh, pbl;
    const float4 zf4 = make_float4(0.f, 0.f, 0.f, 0.f);

    // prologue: load tile k0=0 into registers
#pragma unroll
    for (int i = 0; i < 4; i++) {
        int grow = brow + ra[i];
        pa[i] = (grow < M) ? *(const float4*)(A + (size_t)grow * K + ca[i] * 4) : zf4;
    }
    pbh = *(const uint4*)(Bh + (size_t)(bcol + rb) * K + cb * 8);
    pbl = *(const uint4*)(Bl + (size_t)(bcol + rb) * K + cb * 8);

    for (int k0 = 0; k0 < K; k0 += 32) {
        // ---- store prefetched tile to smem (A split hi/lo here)
#pragma unroll
        for (int i = 0; i < 4; i++) {
            float4 v = pa[i];
            __nv_bfloat162 l01, l23;
            __nv_bfloat162 h01 = split_pair(v.x, v.y, l01);
            __nv_bfloat162 h23 = split_pair(v.z, v.w, l23);
            int o = ra[i] * ASTR + ca[i] * 4;
            *(__nv_bfloat162*)&sAh[o]     = h01;
            *(__nv_bfloat162*)&sAh[o + 2] = h23;
            *(__nv_bfloat162*)&sAl[o]     = l01;
            *(__nv_bfloat162*)&sAl[o + 2] = l23;
        }
        ((uint4*)sBh)[rb * 5 + cb] = pbh;   // ASTR bf16 = 5 uint4
        ((uint4*)sBl)[rb * 5 + cb] = pbl;
        __syncthreads();

        // ---- prefetch next tile into registers (overlaps with MMA below)
        if (k0 + 32 < K) {
            int kn = k0 + 32;
#pragma unroll
            for (int i = 0; i < 4; i++) {
                int grow = brow + ra[i];
                pa[i] = (grow < M) ? *(const float4*)(A + (size_t)grow * K + kn + ca[i] * 4) : zf4;
            }
            pbh = *(const uint4*)(Bh + (size_t)(bcol + rb) * K + kn + cb * 8);
            pbl = *(const uint4*)(Bl + (size_t)(bcol + rb) * K + kn + cb * 8);
        }

        // ---- compute 32 k-values (2 MMA k-steps), 3-MMA split
#pragma unroll
        for (int ks = 0; ks < 32; ks += 16) {
            unsigned ah[2][4], al[2][4], bh[2][4], bl[2][4];
            ldsm_x4(ah[0], aBaseH + (unsigned)(ks) * 2);
            ldsm_x4(ah[1], aBaseH + (unsigned)(16 * ASTR + ks) * 2);
            ldsm_x4(al[0], aBaseL + (unsigned)(ks) * 2);
            ldsm_x4(al[1], aBaseL + (unsigned)(16 * ASTR + ks) * 2);
            ldsm_x4(bh[0], bBaseH + (unsigned)(ks) * 2);
            ldsm_x4(bh[1], bBaseH + (unsigned)(16 * ASTR + ks) * 2);
            ldsm_x4(bl[0], bBaseL + (unsigned)(ks) * 2);
            ldsm_x4(bl[1], bBaseL + (unsigned)(16 * ASTR + ks) * 2);
#pragma unroll
            for (int mi = 0; mi < 2; mi++) {
#pragma unroll
                for (int j = 0; j < 4; j++) {
                    const unsigned* bhp = &bh[j >> 1][(j & 1) * 2];
                    const unsigned* blp = &bl[j >> 1][(j & 1) * 2];
                    mma_bf16(acc[mi][j], ah[mi], bhp);
                    mma_bf16(acc[mi][j], ah[mi], blp);
                    mma_bf16(acc[mi][j], al[mi], bhp);
                }
            }
        }
        __syncthreads();
    }

    // ---- epilogue
    int r_base = brow + warp_m * 32 + (lane >> 2);
    int c_base = bcol + warp_n * 32 + (lane & 3) * 2;
#pragma unroll
    for (int mi = 0; mi < 2; mi++) {
#pragma unroll
        for (int j = 0; j < 4; j++) {
            int cc = c_base + j * 8;
            int r0 = r_base + mi * 16;
            if (r0 < M)
                *(float2*)(C + (size_t)r0 * N + cc) = make_float2(acc[mi][j][0], acc[mi][j][1]);
            int r1 = r0 + 8;
            if (r1 < M)
                *(float2*)(C + (size_t)r1 * N + cc) = make_float2(acc[mi][j][2], acc[mi][j][3]);
        }
    }
}

// ---------------- CSR gather-sum ------------------------------------------------
// layer1: sum fp32 s1 rows -> relu -> fp32 h. 64 float4 lanes/node.
__global__ void gather1_kernel(int n) {
    int i = blockIdx.x * blockDim.x + threadIdx.x;
    int node = i >> 6;
    if (node >= n) return;
    int c = i & 63;
    const float4* sup = (const float4*)g_s1;
    int beg = g_row[node];
    int end = g_row[node + 1];
    float4 acc = make_float4(0.f, 0.f, 0.f, 0.f);
    int j = beg;
    for (; j + 1 < end; j += 2) {
        int s0 = g_csr_src[j];
        int s1 = g_csr_src[j + 1];
        float4 v0 = sup[((size_t)s0 << 6) + c];
        float4 v1 = sup[((size_t)s1 << 6) + c];
        acc.x += v0.x + v1.x; acc.y += v0.y + v1.y;
        acc.z += v0.z + v1.z; acc.w += v0.w + v1.w;
    }
    if (j < end) {
        int s0 = g_csr_src[j];
        float4 v0 = sup[((size_t)s0 << 6) + c];
        acc.x += v0.x; acc.y += v0.y; acc.z += v0.z; acc.w += v0.w;
    }
    acc.x = fmaxf(acc.x, 0.f); acc.y = fmaxf(acc.y, 0.f);
    acc.z = fmaxf(acc.z, 0.f); acc.w = fmaxf(acc.w, 0.f);
    ((float4*)g_h)[((size_t)node << 6) + c] = acc;
}

// layer2: sum fp32 s2 rows -> d_out (fp32). 32 float4 lanes/node.
__global__ void gather2_kernel(float4* __restrict__ out, int n) {
    int i = blockIdx.x * blockDim.x + threadIdx.x;
    int node = i >> 5;
    if (node >= n) return;
    int c = i & 31;
    const float4* sup = (const float4*)g_s2;
    int beg = g_row[node];
    int end = g_row[node + 1];
    float4 acc = make_float4(0.f, 0.f, 0.f, 0.f);
    int j = beg;
    for (; j + 1 < end; j += 2) {
        int s0 = g_csr_src[j];
        int s1 = g_csr_src[j + 1];
        float4 v0 = sup[((size_t)s0 << 5) + c];
        float4 v1 = sup[((size_t)s1 << 5) + c];
        acc.x += v0.x + v1.x; acc.y += v0.y + v1.y;
        acc.z += v0.z + v1.z; acc.w += v0.w + v1.w;
    }
    if (j < end) {
        int s0 = g_csr_src[j];
        float4 v0 = sup[((size_t)s0 << 5) + c];
        acc.x += v0.x; acc.y += v0.y; acc.z += v0.z; acc.w += v0.w;
    }
    out[((size_t)node << 5) + c] = acc;
}

// ---------------- launch --------------------------------------------------------
extern "C" void kernel_launch(void* const* d_in, const int* in_sizes, int n_in,
                              void* d_out, int out_size) {
    const float* x    = (const float*)d_in[0];
    const float* w1   = (const float*)d_in[1];
    const float* w2   = (const float*)d_in[2];
    const int*   esrc = (const int*)d_in[3];
    const int*   edst = (const int*)d_in[4];
    int n  = in_sizes[0] / NFEAT;
    int ne = in_sizes[3];

    __nv_bfloat16 *w1h, *w1l, *w2h, *w2l;
    float *s1, *s2, *h;
    cudaGetSymbolAddress((void**)&w1h, g_w1h);
    cudaGetSymbolAddress((void**)&w1l, g_w1l);
    cudaGetSymbolAddress((void**)&w2h, g_w2h);
    cudaGetSymbolAddress((void**)&w2l, g_w2l);
    cudaGetSymbolAddress((void**)&s1,  g_s1);
    cudaGetSymbolAddress((void**)&s2,  g_s2);
    cudaGetSymbolAddress((void**)&h,   g_h);

    // lazily create side stream + capture-safe events (host objects, no device mem)
    static cudaStream_t sSide = nullptr;
    static cudaEvent_t eFork = nullptr, ePrep = nullptr, eCsr = nullptr;
    if (!sSide) {
        cudaStreamCreateWithFlags(&sSide, cudaStreamNonBlocking);
        cudaEventCreateWithFlags(&eFork, cudaEventDisableTiming);
        cudaEventCreateWithFlags(&ePrep, cudaEventDisableTiming);
        cudaEventCreateWithFlags(&eCsr,  cudaEventDisableTiming);
    }

    // fork side stream from the (captured) main stream
    cudaEventRecord(eFork, 0);
    cudaStreamWaitEvent(sSide, eFork, 0);

    // side stream: weight splits, then CSR build — hides under gemm1
    split_wt_kernel<<<(NFEAT * NHID + 255) / 256, 256, 0, sSide>>>(w1, w1h, w1l, NFEAT, NHID);
    split_wt_kernel<<<(NHID * NOUT + 255) / 256, 256, 0, sSide>>>(w2, w2h, w2l, NHID, NOUT);
    cudaEventRecord(ePrep, sSide);
    zero_count_kernel<<<(n + 255) / 256, 256, 0, sSide>>>(n);
    hist_kernel<<<(ne / 4 + 255) / 256, 256, 0, sSide>>>(edst, ne);
    scan_kernel<<<1, 1024, 0, sSide>>>(n);
    fill_kernel<<<(ne / 4 + 255) / 256, 256, 0, sSide>>>(esrc, edst, ne);
    cudaEventRecord(eCsr, sSide);

    // main stream: gemm1 (needs w1 split) -> gather1 (needs CSR) -> gemm2 -> gather2
    cudaStreamWaitEvent(0, ePrep, 0);
    gemm_bf16x3_kernel<<<dim3(NHID / 64, (n + 127) / 128), 256>>>(x, w1h, w1l, s1, n, NHID, NFEAT);
    cudaStreamWaitEvent(0, eCsr, 0);
    gather1_kernel<<<(n * 64 + 255) / 256, 256>>>(n);
    gemm_bf16x3_kernel<<<dim3(NOUT / 64, (n + 127) / 128), 256>>>(h, w2h, w2l, s2, n, NOUT, NHID);
    gather2_kernel<<<(n * 32 + 255) / 256, 256>>>((float4*)d_out, n);
}